// round 6
// baseline (speedup 1.0000x reference)
#include <cuda_runtime.h>

// Problem constants (fixed shapes)
constexpr int BATCH  = 8;
constexpr int SEQ    = 4096;
constexpr int NODES  = BATCH * SEQ;     // 32768
constexpr int HD     = 128;
constexpr int NE     = 524288;
constexpr int RELS   = 8;
constexpr int LAYERS = 2;

// Scratch (device globals; no dynamic allocation allowed)
__device__ float g_x[(size_t)NODES * HD];            // node states          16.8 MB
__device__ float g_y[(size_t)RELS * NODES * HD];     // per-relation x@Wr^T 134.2 MB
__device__ float g_self[(size_t)NODES * HD];         // x@Ws^T + b           16.8 MB
__device__ float g_agg[(size_t)NODES * HD];          // message accumulator  16.8 MB
__device__ float g_deg[NODES];

// ---------------------------------------------------------------------------
// small utility kernels
// ---------------------------------------------------------------------------
__global__ void k_zero_deg() {
    int i = blockIdx.x * blockDim.x + threadIdx.x;
    if (i < NODES) g_deg[i] = 0.0f;
}

__global__ void k_deg(const int* __restrict__ dst) {
    int e = blockIdx.x * blockDim.x + threadIdx.x;
    if (e < NE) atomicAdd(&g_deg[dst[e]], 1.0f);
}

__global__ void k_zero_agg() {
    int t = blockIdx.x * blockDim.x + threadIdx.x;   // grid covers NODES*HD/4 exactly
    ((float4*)g_agg)[t] = make_float4(0.f, 0.f, 0.f, 0.f);
}

// ---------------------------------------------------------------------------
// GEMM config: C[M,N] = A[M,K] * W[N,K]^T   (NT, both K-contiguous)
// BM=BN=128, BK=32, 256 threads, 8x8 microtile per thread
// ---------------------------------------------------------------------------
constexpr int BM = 128, BN = 128, BK = 32;

// embed + projection: A[m][k] = concept_emb[cid[m]][k] + kind_emb[kid[m]][k]
// C = g_x = A @ proj_W^T + proj_b
__global__ __launch_bounds__(256, 2)
void k_embed_proj(const int* __restrict__ cids, const int* __restrict__ kids,
                  const float* __restrict__ cemb, const float* __restrict__ kemb,
                  const float* __restrict__ W, const float* __restrict__ bias) {
    __shared__ float As[BK][BM];
    __shared__ float Bs[BK][BN];
    const int m0  = blockIdx.x * BM;
    const int tid = threadIdx.x;
    const int lr  = tid >> 3;          // 0..31
    const int lc  = (tid & 7) << 2;    // 0,4,...,28
    const int row = (tid >> 4) << 3;   // 0..120
    const int col = (tid & 15) << 3;   // 0..120

    float acc[8][8];
#pragma unroll
    for (int i = 0; i < 8; i++)
#pragma unroll
        for (int j = 0; j < 8; j++) acc[i][j] = 0.0f;

    for (int k0 = 0; k0 < HD; k0 += BK) {
#pragma unroll
        for (int rr = 0; rr < BM; rr += 32) {
            int m = m0 + lr + rr;
            int cid = cids[m];
            int kid = kids[m];
            float4 a = *(const float4*)(cemb + (size_t)cid * HD + k0 + lc);
            float4 b = *(const float4*)(kemb + (size_t)kid * HD + k0 + lc);
            As[lc + 0][lr + rr] = a.x + b.x;
            As[lc + 1][lr + rr] = a.y + b.y;
            As[lc + 2][lr + rr] = a.z + b.z;
            As[lc + 3][lr + rr] = a.w + b.w;
            float4 w = *(const float4*)(W + (size_t)(lr + rr) * HD + k0 + lc);
            Bs[lc + 0][lr + rr] = w.x;
            Bs[lc + 1][lr + rr] = w.y;
            Bs[lc + 2][lr + rr] = w.z;
            Bs[lc + 3][lr + rr] = w.w;
        }
        __syncthreads();
#pragma unroll
        for (int k = 0; k < BK; k++) {
            float a[8], b[8];
            *(float4*)(a)     = *(const float4*)&As[k][row];
            *(float4*)(a + 4) = *(const float4*)&As[k][row + 4];
            *(float4*)(b)     = *(const float4*)&Bs[k][col];
            *(float4*)(b + 4) = *(const float4*)&Bs[k][col + 4];
#pragma unroll
            for (int i = 0; i < 8; i++)
#pragma unroll
                for (int j = 0; j < 8; j++) acc[i][j] += a[i] * b[j];
        }
        __syncthreads();
    }
#pragma unroll
    for (int i = 0; i < 8; i++) {
        float* cp = g_x + (size_t)(m0 + row + i) * HD + col;
        float4 o0, o1;
        o0.x = acc[i][0] + bias[col + 0];
        o0.y = acc[i][1] + bias[col + 1];
        o0.z = acc[i][2] + bias[col + 2];
        o0.w = acc[i][3] + bias[col + 3];
        o1.x = acc[i][4] + bias[col + 4];
        o1.y = acc[i][5] + bias[col + 5];
        o1.z = acc[i][6] + bias[col + 6];
        o1.w = acc[i][7] + bias[col + 7];
        *(float4*)(cp)     = o0;
        *(float4*)(cp + 4) = o1;
    }
}

// layer GEMM: blockIdx.y = j; j<8 -> y_j = x @ rel_W[l,j]^T ; j==8 -> g_self = x @ self_W[l]^T + self_b[l]
__global__ __launch_bounds__(256, 2)
void k_layer_gemm(const float* __restrict__ relW, const float* __restrict__ selfW,
                  const float* __restrict__ selfb, int l) {
    __shared__ float As[BK][BM];
    __shared__ float Bs[BK][BN];
    const int j = blockIdx.y;
    const float* W;
    float* C;
    const float* bias;
    if (j < RELS) {
        W = relW + ((size_t)(l * RELS + j)) * HD * HD;
        C = g_y + (size_t)j * NODES * HD;
        bias = nullptr;
    } else {
        W = selfW + (size_t)l * HD * HD;
        C = g_self;
        bias = selfb + (size_t)l * HD;
    }
    const int m0  = blockIdx.x * BM;
    const int tid = threadIdx.x;
    const int lr  = tid >> 3;
    const int lc  = (tid & 7) << 2;
    const int row = (tid >> 4) << 3;
    const int col = (tid & 15) << 3;

    float acc[8][8];
#pragma unroll
    for (int i = 0; i < 8; i++)
#pragma unroll
        for (int jj = 0; jj < 8; jj++) acc[i][jj] = 0.0f;

    for (int k0 = 0; k0 < HD; k0 += BK) {
#pragma unroll
        for (int rr = 0; rr < BM; rr += 32) {
            float4 v = *(const float4*)(g_x + (size_t)(m0 + lr + rr) * HD + k0 + lc);
            As[lc + 0][lr + rr] = v.x;
            As[lc + 1][lr + rr] = v.y;
            As[lc + 2][lr + rr] = v.z;
            As[lc + 3][lr + rr] = v.w;
            float4 w = *(const float4*)(W + (size_t)(lr + rr) * HD + k0 + lc);
            Bs[lc + 0][lr + rr] = w.x;
            Bs[lc + 1][lr + rr] = w.y;
            Bs[lc + 2][lr + rr] = w.z;
            Bs[lc + 3][lr + rr] = w.w;
        }
        __syncthreads();
#pragma unroll
        for (int k = 0; k < BK; k++) {
            float a[8], b[8];
            *(float4*)(a)     = *(const float4*)&As[k][row];
            *(float4*)(a + 4) = *(const float4*)&As[k][row + 4];
            *(float4*)(b)     = *(const float4*)&Bs[k][col];
            *(float4*)(b + 4) = *(const float4*)&Bs[k][col + 4];
#pragma unroll
            for (int i = 0; i < 8; i++)
#pragma unroll
                for (int jj = 0; jj < 8; jj++) acc[i][jj] += a[i] * b[jj];
        }
        __syncthreads();
    }
#pragma unroll
    for (int i = 0; i < 8; i++) {
        float* cp = C + (size_t)(m0 + row + i) * HD + col;
        float4 o0, o1;
        if (bias) {
            o0.x = acc[i][0] + bias[col + 0];
            o0.y = acc[i][1] + bias[col + 1];
            o0.z = acc[i][2] + bias[col + 2];
            o0.w = acc[i][3] + bias[col + 3];
            o1.x = acc[i][4] + bias[col + 4];
            o1.y = acc[i][5] + bias[col + 5];
            o1.z = acc[i][6] + bias[col + 6];
            o1.w = acc[i][7] + bias[col + 7];
        } else {
            o0.x = acc[i][0]; o0.y = acc[i][1]; o0.z = acc[i][2]; o0.w = acc[i][3];
            o1.x = acc[i][4]; o1.y = acc[i][5]; o1.z = acc[i][6]; o1.w = acc[i][7];
        }
        *(float4*)(cp)     = o0;
        *(float4*)(cp + 4) = o1;
    }
}

// ---------------------------------------------------------------------------
// edge scatter: one warp per edge, agg[dst] += y[et][src]  (float4 atomics)
// ---------------------------------------------------------------------------
__global__ void k_scatter(const int* __restrict__ src, const int* __restrict__ dst,
                          const int* __restrict__ et) {
    int t = blockIdx.x * blockDim.x + threadIdx.x;  // grid covers NE*32 exactly
    int e = t >> 5;
    int lane = t & 31;
    int s = src[e];
    int d = dst[e];
    int r = et[e];
    float4 v = ((const float4*)(g_y + ((size_t)r * NODES + s) * HD))[lane];
    atomicAdd(((float4*)(g_agg + (size_t)d * HD)) + lane, v);
}

// x = relu(self + agg / max(deg,1))
__global__ void k_update() {
    int t = blockIdx.x * blockDim.x + threadIdx.x;  // grid covers NODES*HD/4 exactly
    int node = t >> 5;                              // 32 float4 per node
    float invd = 1.0f / fmaxf(g_deg[node], 1.0f);
    float4 a = ((const float4*)g_agg)[t];
    float4 s = ((const float4*)g_self)[t];
    float4 o;
    o.x = fmaxf(fmaf(a.x, invd, s.x), 0.0f);
    o.y = fmaxf(fmaf(a.y, invd, s.y), 0.0f);
    o.z = fmaxf(fmaf(a.z, invd, s.z), 0.0f);
    o.w = fmaxf(fmaf(a.w, invd, s.w), 0.0f);
    ((float4*)g_x)[t] = o;
}

__global__ void k_output(const int* __restrict__ mask, float* __restrict__ out) {
    int t = blockIdx.x * blockDim.x + threadIdx.x;  // grid covers NODES*HD/4 exactly
    float m = (float)mask[t >> 5];
    float4 x = ((const float4*)g_x)[t];
    x.x *= m; x.y *= m; x.z *= m; x.w *= m;
    ((float4*)out)[t] = x;
}

// ---------------------------------------------------------------------------
// launch
// ---------------------------------------------------------------------------
extern "C" void kernel_launch(void* const* d_in, const int* in_sizes, int n_in,
                              void* d_out, int out_size) {
    (void)in_sizes; (void)n_in; (void)out_size;
    const int*   cids  = (const int*)d_in[0];
    const int*   kids  = (const int*)d_in[1];
    const int*   mask  = (const int*)d_in[2];
    const int*   eidx  = (const int*)d_in[3];
    const int*   etype = (const int*)d_in[4];
    const float* cemb  = (const float*)d_in[5];
    const float* kemb  = (const float*)d_in[6];
    const float* projW = (const float*)d_in[7];
    const float* projb = (const float*)d_in[8];
    const float* selfW = (const float*)d_in[9];
    const float* selfb = (const float*)d_in[10];
    const float* relW  = (const float*)d_in[11];
    const int* src = eidx;
    const int* dst = eidx + NE;

    const int VEC = NODES * HD / 4;  // 1048576

    k_zero_deg<<<NODES / 256, 256>>>();
    k_deg<<<NE / 256, 256>>>(dst);
    k_embed_proj<<<NODES / BM, 256>>>(cids, kids, cemb, kemb, projW, projb);

    for (int l = 0; l < LAYERS; l++) {
        k_layer_gemm<<<dim3(NODES / BM, RELS + 1), 256>>>(relW, selfW, selfb, l);
        k_zero_agg<<<VEC / 256, 256>>>();
        k_scatter<<<(NE * 32) / 256, 256>>>(src, dst, etype);
        k_update<<<VEC / 256, 256>>>();
    }

    k_output<<<VEC / 256, 256>>>(mask, (float*)d_out);
}

// round 9
// speedup vs baseline: 1.6584x; 1.6584x over previous
#include <cuda_runtime.h>
#include <cuda_bf16.h>
#include <cstdint>

// Problem constants (fixed shapes)
constexpr int BATCH  = 8;
constexpr int SEQ    = 4096;
constexpr int NODES  = BATCH * SEQ;     // 32768
constexpr int HD     = 128;
constexpr int NE     = 524288;
constexpr int RELS   = 8;
constexpr int LAYERS = 2;
constexpr int NMAT   = RELS + 1;        // 8 rel + 1 self per layer

// Scratch (device globals; no dynamic allocation allowed)
__device__ float g_x[(size_t)NODES * HD];            // node states          16.8 MB
__device__ float g_y[(size_t)RELS * NODES * HD];     // per-relation x@Wr^T 134.2 MB
__device__ float g_self[(size_t)NODES * HD];         // x@Ws^T + b           16.8 MB
__device__ float g_agg[(size_t)NODES * HD];          // message accumulator  16.8 MB
__device__ float g_deg[NODES];
__device__ __nv_bfloat16 g_xhi[(size_t)NODES * HD];  // split node states (bf16 hi/lo)
__device__ __nv_bfloat16 g_xlo[(size_t)NODES * HD];
__device__ __nv_bfloat16 g_whi[(size_t)LAYERS * NMAT * HD * HD];
__device__ __nv_bfloat16 g_wlo[(size_t)LAYERS * NMAT * HD * HD];

// ---------------------------------------------------------------------------
// PTX helpers: ldmatrix + mma.sync (sm_80+ features; legal on plain sm_103)
// ---------------------------------------------------------------------------
__device__ __forceinline__ uint32_t smem_u32(const void* p) {
    uint32_t a;
    asm("{ .reg .u64 t; cvta.to.shared.u64 t, %1; cvt.u32.u64 %0, t; }"
        : "=r"(a) : "l"(p));
    return a;
}

__device__ __forceinline__ void ldsm_x4(uint32_t* r, uint32_t addr) {
    asm volatile("ldmatrix.sync.aligned.m8n8.x4.shared.b16 {%0,%1,%2,%3}, [%4];"
                 : "=r"(r[0]), "=r"(r[1]), "=r"(r[2]), "=r"(r[3]) : "r"(addr));
}
__device__ __forceinline__ void ldsm_x2(uint32_t* r, uint32_t addr) {
    asm volatile("ldmatrix.sync.aligned.m8n8.x2.shared.b16 {%0,%1}, [%2];"
                 : "=r"(r[0]), "=r"(r[1]) : "r"(addr));
}

// D += A(16x16,row) * B(16x8,col), bf16 inputs, f32 accum
__device__ __forceinline__ void mma16816(float* d, const uint32_t* a, const uint32_t* b) {
    asm volatile(
        "mma.sync.aligned.m16n8k16.row.col.f32.bf16.bf16.f32 "
        "{%0,%1,%2,%3}, {%4,%5,%6,%7}, {%8,%9}, {%0,%1,%2,%3};"
        : "+f"(d[0]), "+f"(d[1]), "+f"(d[2]), "+f"(d[3])
        : "r"(a[0]), "r"(a[1]), "r"(a[2]), "r"(a[3]), "r"(b[0]), "r"(b[1]));
}

// ---------------------------------------------------------------------------
// small utility kernels
// ---------------------------------------------------------------------------
__global__ void k_zero_deg() {
    int i = blockIdx.x * blockDim.x + threadIdx.x;
    if (i < NODES) g_deg[i] = 0.0f;
}

__global__ void k_deg(const int* __restrict__ dst) {
    int e = blockIdx.x * blockDim.x + threadIdx.x;
    if (e < NE) atomicAdd(&g_deg[dst[e]], 1.0f);
}

__global__ void k_zero_agg() {
    int t = blockIdx.x * blockDim.x + threadIdx.x;   // grid covers NODES*HD/4 exactly
    ((float4*)g_agg)[t] = make_float4(0.f, 0.f, 0.f, 0.f);
}

// split weights: layout [l][j(0..8)][128][128], j==8 is self_W
__global__ void k_split_w(const float* __restrict__ relW, const float* __restrict__ selfW) {
    int t = blockIdx.x * blockDim.x + threadIdx.x;   // LAYERS*9*HD*HD threads
    int mat = t / (HD * HD);
    int pos = t % (HD * HD);
    int l = mat / NMAT, j = mat % NMAT;
    float v = (j < RELS) ? relW[(size_t)(l * RELS + j) * HD * HD + pos]
                         : selfW[(size_t)l * HD * HD + pos];
    __nv_bfloat16 h = __float2bfloat16(v);
    g_whi[t] = h;
    g_wlo[t] = __float2bfloat16(v - __bfloat162float(h));
}

// ---------------------------------------------------------------------------
// fp32 SIMT GEMM for the input projection (accuracy-critical, small share).
// C = g_x = (cemb[cid]+kemb[kid]) @ proj_W^T + proj_b ; also writes bf16 splits.
// ---------------------------------------------------------------------------
constexpr int BM = 128, BN = 128, BK = 32;

__global__ __launch_bounds__(256, 2)
void k_embed_proj(const int* __restrict__ cids, const int* __restrict__ kids,
                  const float* __restrict__ cemb, const float* __restrict__ kemb,
                  const float* __restrict__ W, const float* __restrict__ bias) {
    __shared__ float As[BK][BM];
    __shared__ float Bs[BK][BN];
    const int m0  = blockIdx.x * BM;
    const int tid = threadIdx.x;
    const int lr  = tid >> 3;
    const int lc  = (tid & 7) << 2;
    const int row = (tid >> 4) << 3;
    const int col = (tid & 15) << 3;

    float acc[8][8];
#pragma unroll
    for (int i = 0; i < 8; i++)
#pragma unroll
        for (int j = 0; j < 8; j++) acc[i][j] = 0.0f;

    for (int k0 = 0; k0 < HD; k0 += BK) {
#pragma unroll
        for (int rr = 0; rr < BM; rr += 32) {
            int m = m0 + lr + rr;
            int cid = cids[m];
            int kid = kids[m];
            float4 a = *(const float4*)(cemb + (size_t)cid * HD + k0 + lc);
            float4 b = *(const float4*)(kemb + (size_t)kid * HD + k0 + lc);
            As[lc + 0][lr + rr] = a.x + b.x;
            As[lc + 1][lr + rr] = a.y + b.y;
            As[lc + 2][lr + rr] = a.z + b.z;
            As[lc + 3][lr + rr] = a.w + b.w;
            float4 w = *(const float4*)(W + (size_t)(lr + rr) * HD + k0 + lc);
            Bs[lc + 0][lr + rr] = w.x;
            Bs[lc + 1][lr + rr] = w.y;
            Bs[lc + 2][lr + rr] = w.z;
            Bs[lc + 3][lr + rr] = w.w;
        }
        __syncthreads();
#pragma unroll
        for (int k = 0; k < BK; k++) {
            float a[8], b[8];
            *(float4*)(a)     = *(const float4*)&As[k][row];
            *(float4*)(a + 4) = *(const float4*)&As[k][row + 4];
            *(float4*)(b)     = *(const float4*)&Bs[k][col];
            *(float4*)(b + 4) = *(const float4*)&Bs[k][col + 4];
#pragma unroll
            for (int i = 0; i < 8; i++)
#pragma unroll
                for (int j = 0; j < 8; j++) acc[i][j] += a[i] * b[j];
        }
        __syncthreads();
    }
#pragma unroll
    for (int i = 0; i < 8; i++) {
        size_t base = (size_t)(m0 + row + i) * HD + col;
        float o[8];
#pragma unroll
        for (int j = 0; j < 8; j++) o[j] = acc[i][j] + bias[col + j];
        *(float4*)(g_x + base)     = make_float4(o[0], o[1], o[2], o[3]);
        *(float4*)(g_x + base + 4) = make_float4(o[4], o[5], o[6], o[7]);
#pragma unroll
        for (int p = 0; p < 4; p++) {
            __nv_bfloat16 h0 = __float2bfloat16(o[2 * p]);
            __nv_bfloat16 h1 = __float2bfloat16(o[2 * p + 1]);
            __nv_bfloat16 l0 = __float2bfloat16(o[2 * p]     - __bfloat162float(h0));
            __nv_bfloat16 l1 = __float2bfloat16(o[2 * p + 1] - __bfloat162float(h1));
            *(__nv_bfloat162*)(g_xhi + base + 2 * p) = __halves2bfloat162(h0, h1);
            *(__nv_bfloat162*)(g_xlo + base + 2 * p) = __halves2bfloat162(l0, l1);
        }
    }
}

// ---------------------------------------------------------------------------
// Tensor-core GEMM (mma.sync bf16, 3x split, fp32 accum).
// Grid = 256 CTAs (one 128-row m-tile each); j-loop over 9 weight matrices,
// A tiles stay resident in SMEM. Warp tile 64x32, 8 warps.
// ---------------------------------------------------------------------------
constexpr int LDT = 136;                         // padded bf16 row stride (272 B)
constexpr int MMA_SMEM = 4 * 128 * LDT * 2;      // Ahi,Alo,Whi,Wlo = 139264 B

__global__ __launch_bounds__(256, 1)
void k_mma_gemm(const float* __restrict__ selfb, int l) {
    extern __shared__ __nv_bfloat16 sm[];
    __nv_bfloat16* sAhi = sm;
    __nv_bfloat16* sAlo = sm + 128 * LDT;
    __nv_bfloat16* sWhi = sm + 2 * 128 * LDT;
    __nv_bfloat16* sWlo = sm + 3 * 128 * LDT;

    const int tid  = threadIdx.x;
    const int wid  = tid >> 5;
    const int lane = tid & 31;
    const int m0   = blockIdx.x * 128;
    const int mw   = (wid >> 2) * 64;    // warp m offset (0/64)
    const int nw   = (wid & 3) * 32;     // warp n offset (0..96)

    // fill A tiles once (each thread: 16B chunks, coalesced)
    {
        int row = tid >> 4, ch = tid & 15;
        for (int rr = 0; rr < 128; rr += 16) {
            uint4 vh = ((const uint4*)(g_xhi + (size_t)(m0 + row + rr) * HD))[ch];
            uint4 vl = ((const uint4*)(g_xlo + (size_t)(m0 + row + rr) * HD))[ch];
            *(uint4*)(sAhi + (row + rr) * LDT + ch * 8) = vh;
            *(uint4*)(sAlo + (row + rr) * LDT + ch * 8) = vl;
        }
    }

    const uint32_t aAhi = smem_u32(sAhi), aAlo = smem_u32(sAlo);
    const uint32_t aWhi = smem_u32(sWhi), aWlo = smem_u32(sWlo);

    // ldmatrix lane addressing
    const int a_row  = lane & 15;
    const int a_koff = (lane >> 4) * 8;
    const int b_row  = lane & 7;
    const int b_koff = ((lane >> 3) & 1) * 8;

    for (int j = 0; j < NMAT; j++) {
        if (j) __syncthreads();          // prior j's mma reads done before refill
        {
            const __nv_bfloat16* Whg = g_whi + (size_t)(l * NMAT + j) * HD * HD;
            const __nv_bfloat16* Wlg = g_wlo + (size_t)(l * NMAT + j) * HD * HD;
            int row = tid >> 4, ch = tid & 15;
            for (int rr = 0; rr < 128; rr += 16) {
                uint4 vh = ((const uint4*)(Whg + (size_t)(row + rr) * HD))[ch];
                uint4 vl = ((const uint4*)(Wlg + (size_t)(row + rr) * HD))[ch];
                *(uint4*)(sWhi + (row + rr) * LDT + ch * 8) = vh;
                *(uint4*)(sWlo + (row + rr) * LDT + ch * 8) = vl;
            }
        }
        __syncthreads();

        float d[4][4][4];
#pragma unroll
        for (int mi = 0; mi < 4; mi++)
#pragma unroll
            for (int ni = 0; ni < 4; ni++)
#pragma unroll
                for (int q = 0; q < 4; q++) d[mi][ni][q] = 0.0f;

        // 3 split terms: hi*hi, hi*lo, lo*hi — all accumulate into d
#pragma unroll
        for (int term = 0; term < 3; term++) {
            const uint32_t aA = (term == 2) ? aAlo : aAhi;
            const uint32_t aW = (term == 1) ? aWlo : aWhi;
#pragma unroll
            for (int k0 = 0; k0 < 128; k0 += 16) {
                uint32_t afr[4][4], bfr[4][2];
#pragma unroll
                for (int mi = 0; mi < 4; mi++)
                    ldsm_x4(afr[mi], aA + ((mw + mi * 16 + a_row) * LDT + k0 + a_koff) * 2);
#pragma unroll
                for (int ni = 0; ni < 4; ni++)
                    ldsm_x2(bfr[ni], aW + ((nw + ni * 8 + b_row) * LDT + k0 + b_koff) * 2);
#pragma unroll
                for (int mi = 0; mi < 4; mi++)
#pragma unroll
                    for (int ni = 0; ni < 4; ni++)
                        mma16816(d[mi][ni], afr[mi], bfr[ni]);
            }
        }

        // epilogue: direct register -> global (float2 stores)
        float* C = (j < RELS) ? g_y + ((size_t)j * NODES + m0) * HD
                              : g_self + (size_t)m0 * HD;
#pragma unroll
        for (int mi = 0; mi < 4; mi++) {
            int r0 = mw + mi * 16 + (lane >> 2);
#pragma unroll
            for (int ni = 0; ni < 4; ni++) {
                int c = nw + ni * 8 + (lane & 3) * 2;
                float b0 = 0.0f, b1 = 0.0f;
                if (j == RELS) {
                    b0 = selfb[l * HD + c];
                    b1 = selfb[l * HD + c + 1];
                }
                *(float2*)(C + (size_t)r0 * HD + c) =
                    make_float2(d[mi][ni][0] + b0, d[mi][ni][1] + b1);
                *(float2*)(C + (size_t)(r0 + 8) * HD + c) =
                    make_float2(d[mi][ni][2] + b0, d[mi][ni][3] + b1);
            }
        }
    }
}

// ---------------------------------------------------------------------------
// edge scatter: one warp per edge, agg[dst] += y[et][src]  (float4 atomics)
// ---------------------------------------------------------------------------
__global__ void k_scatter(const int* __restrict__ src, const int* __restrict__ dst,
                          const int* __restrict__ et) {
    int t = blockIdx.x * blockDim.x + threadIdx.x;  // grid covers NE*32 exactly
    int e = t >> 5;
    int lane = t & 31;
    int s = src[e];
    int d = dst[e];
    int r = et[e];
    float4 v = ((const float4*)(g_y + ((size_t)r * NODES + s) * HD))[lane];
    atomicAdd(((float4*)(g_agg + (size_t)d * HD)) + lane, v);
}

// x = relu(self + agg / max(deg,1)); also writes bf16 splits for next layer
__global__ void k_update() {
    int t = blockIdx.x * blockDim.x + threadIdx.x;  // grid covers NODES*HD/4 exactly
    int node = t >> 5;                              // 32 float4 per node
    float invd = 1.0f / fmaxf(g_deg[node], 1.0f);
    float4 a = ((const float4*)g_agg)[t];
    float4 s = ((const float4*)g_self)[t];
    float4 o;
    o.x = fmaxf(fmaf(a.x, invd, s.x), 0.0f);
    o.y = fmaxf(fmaf(a.y, invd, s.y), 0.0f);
    o.z = fmaxf(fmaf(a.z, invd, s.z), 0.0f);
    o.w = fmaxf(fmaf(a.w, invd, s.w), 0.0f);
    ((float4*)g_x)[t] = o;

    __nv_bfloat16 h0 = __float2bfloat16(o.x), h1 = __float2bfloat16(o.y);
    __nv_bfloat16 h2 = __float2bfloat16(o.z), h3 = __float2bfloat16(o.w);
    __nv_bfloat16 l0 = __float2bfloat16(o.x - __bfloat162float(h0));
    __nv_bfloat16 l1 = __float2bfloat16(o.y - __bfloat162float(h1));
    __nv_bfloat16 l2 = __float2bfloat16(o.z - __bfloat162float(h2));
    __nv_bfloat16 l3 = __float2bfloat16(o.w - __bfloat162float(h3));
    ((__nv_bfloat162*)g_xhi)[t * 2]     = __halves2bfloat162(h0, h1);
    ((__nv_bfloat162*)g_xhi)[t * 2 + 1] = __halves2bfloat162(h2, h3);
    ((__nv_bfloat162*)g_xlo)[t * 2]     = __halves2bfloat162(l0, l1);
    ((__nv_bfloat162*)g_xlo)[t * 2 + 1] = __halves2bfloat162(l2, l3);
}

__global__ void k_output(const int* __restrict__ mask, float* __restrict__ out) {
    int t = blockIdx.x * blockDim.x + threadIdx.x;  // grid covers NODES*HD/4 exactly
    float m = (float)mask[t >> 5];
    float4 x = ((const float4*)g_x)[t];
    x.x *= m; x.y *= m; x.z *= m; x.w *= m;
    ((float4*)out)[t] = x;
}

// ---------------------------------------------------------------------------
// launch
// ---------------------------------------------------------------------------
extern "C" void kernel_launch(void* const* d_in, const int* in_sizes, int n_in,
                              void* d_out, int out_size) {
    (void)in_sizes; (void)n_in; (void)out_size;
    const int*   cids  = (const int*)d_in[0];
    const int*   kids  = (const int*)d_in[1];
    const int*   mask  = (const int*)d_in[2];
    const int*   eidx  = (const int*)d_in[3];
    const int*   etype = (const int*)d_in[4];
    const float* cemb  = (const float*)d_in[5];
    const float* kemb  = (const float*)d_in[6];
    const float* projW = (const float*)d_in[7];
    const float* projb = (const float*)d_in[8];
    const float* selfW = (const float*)d_in[9];
    const float* selfb = (const float*)d_in[10];
    const float* relW  = (const float*)d_in[11];
    const int* src = eidx;
    const int* dst = eidx + NE;

    const int VEC = NODES * HD / 4;  // 1048576

    static bool attr_set = false;
    if (!attr_set) {
        cudaFuncSetAttribute(k_mma_gemm, cudaFuncAttributeMaxDynamicSharedMemorySize,
                             MMA_SMEM);
        attr_set = true;
    }

    k_zero_deg<<<NODES / 256, 256>>>();
    k_deg<<<NE / 256, 256>>>(dst);
    k_embed_proj<<<NODES / BM, 256>>>(cids, kids, cemb, kemb, projW, projb);
    k_split_w<<<(LAYERS * NMAT * HD * HD) / 256, 256>>>(relW, selfW);

    for (int l = 0; l < LAYERS; l++) {
        k_mma_gemm<<<NODES / 128, 256, MMA_SMEM>>>(selfb, l);
        k_zero_agg<<<VEC / 256, 256>>>();
        k_scatter<<<(NE * 32) / 256, 256>>>(src, dst, etype);
        k_update<<<VEC / 256, 256>>>();
    }

    k_output<<<VEC / 256, 256>>>(mask, (float*)d_out);
}